// round 5
// baseline (speedup 1.0000x reference)
#include <cuda_runtime.h>
#include <cstdint>

// EcgFilter_57028575756498
//  Stage 1: order-2 IIR notch filtfilt (edge=9 odd extension) — chunked scans
//           with exponential warm-up (exact chunk-0 init, seam err ~6e-6),
//           warp-cooperative smem-transpose staging for coalesced LDG/STG.
//  Stage 2: 151-tap FIR filtfilt (edge=453) — provably equal to ONE symmetric
//           301-tap convolution with C = autocorr(b_fir) over the +-150
//           odd-extended notch output (zi_fir provably irrelevant).
//
// Inputs: d_in[0]=x(384x120000 f32) [1]=b_notch(3) [2]=a_notch(3)
//         [3]=zi_notch(2) [4]=b_fir(151) [5]=zi_fir(150, unused)
// Output: f32, 384*120000.

typedef unsigned long long u64;

#define T_LEN     120000
#define ROWS      384
#define TE        120018     // T + 2*9 (IIR ext domain)
#define LCH       960        // IIR chunk length (mult of 32)
#define WU        960        // warm-up steps (pole^960 ~ 6e-6)
#define NBATCH    60         // (WU+LCH)/32
#define YF_STRIDE 120032
#define YE_STRIDE 121216
#define MARG      152        // left margin of y1e rows (>=150, mult of 4)
#define TILE      2048
#define NTILE     59         // ceil(T_LEN/TILE)

// -------- scratch (device globals; zero-initialized, no allocation) --------
__device__ __align__(16) float  g_yf [(size_t)ROWS * YF_STRIDE]; // notch fwd (ext domain)
__device__ __align__(16) float  g_y1e[(size_t)ROWS * YE_STRIDE]; // notch filtfilt out + odd-ext margins
__device__ __align__(16) float2 g_Q  [320];                      // packed coeff-pair table

// -------- helpers --------
__device__ __forceinline__ void fma2(u64 &acc, u64 a, u64 b) {
    asm("fma.rn.f32x2 %0, %1, %2, %0;" : "+l"(acc) : "l"(a), "l"(b));
}
__device__ __forceinline__ u64 bcast2(float v) {
    u64 d; unsigned int u = __float_as_uint(v);
    asm("mov.b64 %0, {%1, %1};" : "=l"(d) : "r"(u));
    return d;
}
__device__ __forceinline__ void unpack2(u64 a, float &lo, float &hi) {
    unsigned int l, h;
    asm("mov.b64 {%0, %1}, %2;" : "=r"(l), "=r"(h) : "l"(a));
    lo = __uint_as_float(l); hi = __uint_as_float(h);
}

// ================= K0: autocorrelation + packed pair table =================
// C[j] (j=0..300) = sum_k b[k]*b[k+150-j];  out[t] = sum_j C[j]*y1e[t-150+j].
// Pair table for k_fir: g_Q[m] = ( C[m-8], C[m-9] ), zero outside [0,300].
__global__ void k_coeff(const float* __restrict__ b) {
    __shared__ float sb[151];
    __shared__ float sC[301];
    int t = threadIdx.x;                // 320 threads
    if (t < 151) sb[t] = b[t];
    __syncthreads();
    if (t < 301) {
        int lo = t - 150 > 0 ? t - 150 : 0;
        int hi = t < 150 ? t : 150;
        float acc = 0.0f;
        for (int k = lo; k <= hi; ++k) acc = fmaf(sb[k], sb[k + 150 - t], acc);
        sC[t] = acc;
    }
    __syncthreads();
    if (t < 320) {
        int jx = t - 8, jy = t - 9;
        float vx = (jx >= 0 && jx <= 300) ? sC[jx] : 0.0f;
        float vy = (jy >= 0 && jy <= 300) ? sC[jy] : 0.0f;
        g_Q[t] = make_float2(vx, vy);
    }
}

// ================= IIR step (DF2T, matches reference scan) =================
struct IIRC { float b0, b1, b2, na1, na2; };
__device__ __forceinline__ float iir_step(const IIRC &c, float xv, float &z1, float &z2) {
    float y = fmaf(c.b0, xv, z1);
    float t = fmaf(c.b1, xv, z2);
    z1 = fmaf(c.na1, y, t);
    z2 = fmaf(c.b2, xv, c.na2 * y);
    return y;
}

// ================= K1: notch forward pass (staged) =================
// Block = 1 row, 128 threads = 4 warps; lane l of warp w owns chunk c=32w+l.
// Chunk c covers ext-domain i in [960c, 960c+960); iterates j=0..1919 with
// i = 960(c-1)+j (first 960 = warm-up from z=0; chunk 0 idles then exact-inits).
__global__ __launch_bounds__(128) void k_fwd(const float* __restrict__ x,
                                             const float* __restrict__ bn,
                                             const float* __restrict__ an,
                                             const float* __restrict__ zin) {
    __shared__ float si_[4][32 * 33];
    __shared__ float so_[4][32 * 33];
    int w = threadIdx.x >> 5, l = threadIdx.x & 31;
    int row = blockIdx.x;
    int c = w * 32 + l;
    const float* __restrict__ xr = x + (size_t)row * T_LEN;
    float* __restrict__ yo = g_yf + (size_t)row * YF_STRIDE;
    IIRC cf{bn[0], bn[1], bn[2], -an[1], -an[2]};
    float zn0 = zin[0], zn1 = zin[1];
    float x0 = __ldg(xr), xl = __ldg(xr + T_LEN - 1);
    int base = LCH * (c - 1);
    bool is0 = (c == 0);
    float z1 = 0.0f, z2 = 0.0f;
    float* si = si_[w]; float* so = so_[w];

    for (int b = 0; b < NBATCH; ++b) {
        // stage: iteration k loads 32 consecutive elements of chunk 32w+k
        #pragma unroll 4
        for (int k = 0; k < 32; ++k) {
            int i = LCH * (w * 32 + k - 1) + 32 * b + l;
            int a = i - 9;
            si[k * 33 + l] = (a >= 0 && a < T_LEN) ? __ldg(xr + a) : 0.0f;
        }
        __syncwarp();
        // consume: lane l advances its own chunk 32 steps
        #pragma unroll 4
        for (int e = 0; e < 32; ++e) {
            int i = base + 32 * b + e;
            float xv;
            if (i >= 9 && i < T_LEN + 9)      xv = si[l * 33 + e];
            else if (i < 0)                    xv = 0.0f;
            else if (i < 9)                    xv = 2.0f * x0 - __ldg(xr + 9 - i);
            else if (i < TE)                   xv = 2.0f * xl - __ldg(xr + 2 * T_LEN + 7 - i);
            else                               xv = 0.0f;
            if (is0 && i == 0) { z1 = zn0 * xv; z2 = zn1 * xv; }  // exact zi*ext[0]
            so[l * 33 + e] = iir_step(cf, xv, z1, z2);
        }
        __syncwarp();
        // store main region (b>=30 <=> j>=960 <=> i>=960c)
        if (b >= 30) {
            #pragma unroll 4
            for (int k = 0; k < 32; ++k) {
                int i = LCH * (w * 32 + k - 1) + 32 * b + l;
                if (i < TE) yo[i] = so[k * 33 + l];
            }
        }
        __syncwarp();
    }
}

// ================= K2: notch backward pass (staged) =================
// v[i] = yf[TE-1-i]; output y1[t] at t = T+8-i. Same chunking as k_fwd.
__global__ __launch_bounds__(128) void k_bwd(const float* __restrict__ bn,
                                             const float* __restrict__ an,
                                             const float* __restrict__ zin) {
    __shared__ float si_[4][32 * 33];
    __shared__ float so_[4][32 * 33];
    int w = threadIdx.x >> 5, l = threadIdx.x & 31;
    int row = blockIdx.x;
    int c = w * 32 + l;
    const float* __restrict__ yf = g_yf + (size_t)row * YF_STRIDE;
    float* __restrict__ ye = g_y1e + (size_t)row * YE_STRIDE + MARG;
    IIRC cf{bn[0], bn[1], bn[2], -an[1], -an[2]};
    float zn0 = zin[0], zn1 = zin[1];
    int base = LCH * (c - 1);
    bool is0 = (c == 0);
    float z1 = 0.0f, z2 = 0.0f;
    float* si = si_[w]; float* so = so_[w];

    for (int b = 0; b < NBATCH; ++b) {
        #pragma unroll 4
        for (int k = 0; k < 32; ++k) {
            int i = LCH * (w * 32 + k - 1) + 32 * b + l;
            si[k * 33 + l] = ((unsigned)i < (unsigned)TE) ? __ldg(yf + (TE - 1 - i)) : 0.0f;
        }
        __syncwarp();
        #pragma unroll 4
        for (int e = 0; e < 32; ++e) {
            int i = base + 32 * b + e;
            float xv = ((unsigned)i < (unsigned)TE) ? si[l * 33 + e] : 0.0f;
            if (is0 && i == 0) { z1 = zn0 * xv; z2 = zn1 * xv; }  // exact zi*yf[-1]
            so[l * 33 + e] = iir_step(cf, xv, z1, z2);
        }
        __syncwarp();
        if (b >= 30) {
            #pragma unroll 4
            for (int k = 0; k < 32; ++k) {
                int i = LCH * (w * 32 + k - 1) + 32 * b + l;
                int t = T_LEN + 8 - i;
                if ((unsigned)t < (unsigned)T_LEN) ye[t] = so[k * 33 + l];
            }
        }
        __syncwarp();
    }
}

// ================= K3: odd-extension margins (+-152) for y1e =================
__global__ void k_margin() {
    int row = blockIdx.x;
    int t = threadIdx.x;                        // 0..303
    float* __restrict__ yr = g_y1e + (size_t)row * YE_STRIDE + MARG;
    float y0 = yr[0], yl = yr[T_LEN - 1];
    if (t < MARG) {
        int u = t - MARG;                       // [-152, -1]
        yr[u] = 2.0f * y0 - yr[-u];
    } else {
        int u = T_LEN + (t - MARG);             // [T, T+151]
        yr[u] = 2.0f * yl - yr[2 * T_LEN - 2 - u];
    }
}

// ================= K4: 301-tap symmetric FIR, packed f32x2 =================
// e[i] = g_y1e[row*YE + tb + i] = y1e[tb + i - 152].
// out[tb+p] = sum_dd C2[dd] e[p+dd], C2[dd] = C[dd-2] (support [2,302]).
// acc_k = (out[p0+2k], out[p0+2k+1]); contribution of e[i]: Qt[i-p0-2k],
// Qt[m] = (C2[m], C2[m-1]); table sQ[m] = Qt[m-6] = (C[m-8], C[m-9]).
// Invariant at iter start: q_j = Qt[j-6+4*it]; two refills of 2 pairs per iter
// keep the 8-reg rotation mov-free under unroll 2. e tile XOR-swizzled in
// float4 units (f ^= (f>>3)&7): conflict-free for stride-2-float4 consumers.
__global__ __launch_bounds__(256) void k_fir(float* __restrict__ out) {
    __shared__ float4 se4[592];
    __shared__ ulonglong2 sQ2[160];
    int tid = threadIdx.x;
    int row = blockIdx.y;
    int tb  = blockIdx.x * TILE;

    const float4* __restrict__ gy4 =
        reinterpret_cast<const float4*>(g_y1e + (size_t)row * YE_STRIDE + tb);
    for (int f = tid; f < 588; f += 256) {
        float4 v = gy4[f];
        se4[f ^ ((f >> 3) & 7)] = v;
    }
    if (tid < 160) sQ2[tid] = reinterpret_cast<const ulonglong2*>(g_Q)[tid];
    __syncthreads();

    u64 acc0 = 0, acc1 = 0, acc2 = 0, acc3 = 0;
    ulonglong2 t01 = sQ2[0], t23 = sQ2[1], t45 = sQ2[2], t67 = sQ2[3];
    u64 q0 = t01.x, q1 = t01.y, q2 = t23.x, q3 = t23.y;
    u64 q4 = t45.x, q5 = t45.y, q6 = t67.x, q7 = t67.y;

    int fbase = 2 * tid;
    #pragma unroll 2
    for (int it = 0; it < 78; ++it) {
        int f = fbase + it;
        float4 ev = se4[f ^ ((f >> 3) & 7)];

        u64 e0 = bcast2(ev.x);
        fma2(acc0, q6, e0); fma2(acc1, q4, e0); fma2(acc2, q2, e0); fma2(acc3, q0, e0);
        u64 e1 = bcast2(ev.y);
        fma2(acc0, q7, e1); fma2(acc1, q5, e1); fma2(acc2, q3, e1); fma2(acc3, q1, e1);
        ulonglong2 n1 = sQ2[2 * it + 4];
        q0 = q2; q1 = q3; q2 = q4; q3 = q5; q4 = q6; q5 = q7; q6 = n1.x; q7 = n1.y;

        u64 e2 = bcast2(ev.z);
        fma2(acc0, q6, e2); fma2(acc1, q4, e2); fma2(acc2, q2, e2); fma2(acc3, q0, e2);
        u64 e3 = bcast2(ev.w);
        fma2(acc0, q7, e3); fma2(acc1, q5, e3); fma2(acc2, q3, e3); fma2(acc3, q1, e3);
        ulonglong2 n2 = sQ2[2 * it + 5];
        q0 = q2; q1 = q3; q2 = q4; q3 = q5; q4 = q6; q5 = q7; q6 = n2.x; q7 = n2.y;
    }

    int t0 = tb + tid * 8;
    if (t0 < T_LEN) {                            // T_LEN % 8 == 0 -> all-or-none
        float o0, o1, o2, o3, o4, o5, o6, o7;
        unpack2(acc0, o0, o1); unpack2(acc1, o2, o3);
        unpack2(acc2, o4, o5); unpack2(acc3, o6, o7);
        float4* op = reinterpret_cast<float4*>(out + (size_t)row * T_LEN + t0);
        op[0] = make_float4(o0, o1, o2, o3);
        op[1] = make_float4(o4, o5, o6, o7);
    }
}

// ================= launch =================
extern "C" void kernel_launch(void* const* d_in, const int* in_sizes, int n_in,
                              void* d_out, int out_size) {
    const float* x  = (const float*)d_in[0];
    const float* bn = (const float*)d_in[1];
    const float* an = (const float*)d_in[2];
    const float* zn = (const float*)d_in[3];
    const float* bf = (const float*)d_in[4];
    float* out = (float*)d_out;

    k_coeff<<<1, 320>>>(bf);
    k_fwd<<<ROWS, 128>>>(x, bn, an, zn);
    k_bwd<<<ROWS, 128>>>(bn, an, zn);
    k_margin<<<ROWS, 2 * MARG>>>();
    k_fir<<<dim3(NTILE, ROWS), 256>>>(out);
}

// round 8
// speedup vs baseline: 1.0624x; 1.0624x over previous
#include <cuda_runtime.h>
#include <cstdint>

// EcgFilter_57028575756498  (R8 = audited R6 kernel: static-register coeff
// schedule in k_fir, WU=768)
//  Stage 1: order-2 IIR notch filtfilt (edge=9 odd extension) — chunked scans
//           with exponential warm-up, warp-cooperative smem staging.
//  Stage 2: 151-tap FIR filtfilt == ONE symmetric 301-tap convolution with
//           C = autocorr(b_fir) over the +-150 odd-extended notch output.

typedef unsigned long long u64;

#define T_LEN     120000
#define ROWS      384
#define TE        120018     // T + 2*9 (IIR ext domain)
#define LCH       960        // IIR chunk length (mult of 32)
#define WU        768        // warm-up steps (pole^768 ~ 6.4e-5)
#define NBATCH    54         // (WU+LCH)/32
#define SB        24         // store from batch WU/32
#define YF_STRIDE 120032
#define YE_STRIDE 121216
#define MARG      152        // left margin of y1e rows (>=150, mult of 4)
#define TILE      2048
#define NTILE     59         // ceil(T_LEN/TILE)

// -------- scratch (device globals; zero-initialized, no allocation) --------
__device__ __align__(16) float  g_yf [(size_t)ROWS * YF_STRIDE];
__device__ __align__(16) float  g_y1e[(size_t)ROWS * YE_STRIDE];
__device__ __align__(16) float2 g_Q  [320];   // g_Q[m] = (C[m-8], C[m-9]) = Qt[m-6]

// -------- helpers --------
__device__ __forceinline__ void fma2(u64 &acc, u64 a, u64 b) {
    asm("fma.rn.f32x2 %0, %1, %2, %0;" : "+l"(acc) : "l"(a), "l"(b));
}
__device__ __forceinline__ u64 bcast2(float v) {
    u64 d; unsigned int u = __float_as_uint(v);
    asm("mov.b64 %0, {%1, %1};" : "=l"(d) : "r"(u));
    return d;
}
__device__ __forceinline__ void unpack2(u64 a, float &lo, float &hi) {
    unsigned int l, h;
    asm("mov.b64 {%0, %1}, %2;" : "=r"(l), "=r"(h) : "l"(a));
    lo = __uint_as_float(l); hi = __uint_as_float(h);
}

// ================= K0: autocorrelation + packed pair table =================
__global__ void k_coeff(const float* __restrict__ b) {
    __shared__ float sb[151];
    __shared__ float sC[301];
    int t = threadIdx.x;                // 320 threads
    if (t < 151) sb[t] = b[t];
    __syncthreads();
    if (t < 301) {
        int lo = t - 150 > 0 ? t - 150 : 0;
        int hi = t < 150 ? t : 150;
        float acc = 0.0f;
        for (int k = lo; k <= hi; ++k) acc = fmaf(sb[k], sb[k + 150 - t], acc);
        sC[t] = acc;
    }
    __syncthreads();
    if (t < 320) {
        int jx = t - 8, jy = t - 9;
        float vx = (jx >= 0 && jx <= 300) ? sC[jx] : 0.0f;
        float vy = (jy >= 0 && jy <= 300) ? sC[jy] : 0.0f;
        g_Q[t] = make_float2(vx, vy);
    }
}

// ================= IIR step (DF2T, matches reference scan) =================
struct IIRC { float b0, b1, b2, na1, na2; };
__device__ __forceinline__ float iir_step(const IIRC &c, float xv, float &z1, float &z2) {
    float y = fmaf(c.b0, xv, z1);
    float t = fmaf(c.b1, xv, z2);
    z1 = fmaf(c.na1, y, t);
    z2 = fmaf(c.b2, xv, c.na2 * y);
    return y;
}

// ================= K1: notch forward pass (staged) =================
// Block = 1 row, 4 warps; lane l of warp w owns chunk c=32w+l covering
// ext-domain [960c, 960c+960); scan starts at 960c-768 (warm-up from z=0).
__global__ __launch_bounds__(128) void k_fwd(const float* __restrict__ x,
                                             const float* __restrict__ bn,
                                             const float* __restrict__ an,
                                             const float* __restrict__ zin) {
    __shared__ float si_[4][32 * 33];
    __shared__ float so_[4][32 * 33];
    int w = threadIdx.x >> 5, l = threadIdx.x & 31;
    int row = blockIdx.x;
    int c = w * 32 + l;
    const float* __restrict__ xr = x + (size_t)row * T_LEN;
    float* __restrict__ yo = g_yf + (size_t)row * YF_STRIDE;
    IIRC cf{bn[0], bn[1], bn[2], -an[1], -an[2]};
    float zn0 = zin[0], zn1 = zin[1];
    float x0 = __ldg(xr), xl = __ldg(xr + T_LEN - 1);
    int base = LCH * c - WU;
    bool is0 = (c == 0);
    float z1 = 0.0f, z2 = 0.0f;
    float* si = si_[w]; float* so = so_[w];

    for (int b = 0; b < NBATCH; ++b) {
        #pragma unroll 4
        for (int k = 0; k < 32; ++k) {
            int i = LCH * (w * 32 + k) - WU + 32 * b + l;
            int a = i - 9;
            si[k * 33 + l] = (a >= 0 && a < T_LEN) ? __ldg(xr + a) : 0.0f;
        }
        __syncwarp();
        #pragma unroll 4
        for (int e = 0; e < 32; ++e) {
            int i = base + 32 * b + e;
            float xv;
            if (i >= 9 && i < T_LEN + 9)      xv = si[l * 33 + e];
            else if (i < 0)                    xv = 0.0f;
            else if (i < 9)                    xv = 2.0f * x0 - __ldg(xr + 9 - i);
            else if (i < TE)                   xv = 2.0f * xl - __ldg(xr + 2 * T_LEN + 7 - i);
            else                               xv = 0.0f;
            if (is0 && i == 0) { z1 = zn0 * xv; z2 = zn1 * xv; }  // exact zi*ext[0]
            so[l * 33 + e] = iir_step(cf, xv, z1, z2);
        }
        __syncwarp();
        if (b >= SB) {
            #pragma unroll 4
            for (int k = 0; k < 32; ++k) {
                int i = LCH * (w * 32 + k) - WU + 32 * b + l;
                if (i < TE) yo[i] = so[k * 33 + l];
            }
        }
        __syncwarp();
    }
}

// ================= K2: notch backward pass (staged) =================
// v[i] = yf[TE-1-i]; output y1[t] at t = T+8-i.
__global__ __launch_bounds__(128) void k_bwd(const float* __restrict__ bn,
                                             const float* __restrict__ an,
                                             const float* __restrict__ zin) {
    __shared__ float si_[4][32 * 33];
    __shared__ float so_[4][32 * 33];
    int w = threadIdx.x >> 5, l = threadIdx.x & 31;
    int row = blockIdx.x;
    int c = w * 32 + l;
    const float* __restrict__ yf = g_yf + (size_t)row * YF_STRIDE;
    float* __restrict__ ye = g_y1e + (size_t)row * YE_STRIDE + MARG;
    IIRC cf{bn[0], bn[1], bn[2], -an[1], -an[2]};
    float zn0 = zin[0], zn1 = zin[1];
    int base = LCH * c - WU;
    bool is0 = (c == 0);
    float z1 = 0.0f, z2 = 0.0f;
    float* si = si_[w]; float* so = so_[w];

    for (int b = 0; b < NBATCH; ++b) {
        #pragma unroll 4
        for (int k = 0; k < 32; ++k) {
            int i = LCH * (w * 32 + k) - WU + 32 * b + l;
            si[k * 33 + l] = ((unsigned)i < (unsigned)TE) ? __ldg(yf + (TE - 1 - i)) : 0.0f;
        }
        __syncwarp();
        #pragma unroll 4
        for (int e = 0; e < 32; ++e) {
            int i = base + 32 * b + e;
            float xv = ((unsigned)i < (unsigned)TE) ? si[l * 33 + e] : 0.0f;
            if (is0 && i == 0) { z1 = zn0 * xv; z2 = zn1 * xv; }  // exact zi*yf[-1]
            so[l * 33 + e] = iir_step(cf, xv, z1, z2);
        }
        __syncwarp();
        if (b >= SB) {
            #pragma unroll 4
            for (int k = 0; k < 32; ++k) {
                int i = LCH * (w * 32 + k) - WU + 32 * b + l;
                int t = T_LEN + 8 - i;
                if ((unsigned)t < (unsigned)T_LEN) ye[t] = so[k * 33 + l];
            }
        }
        __syncwarp();
    }
}

// ================= K3: odd-extension margins (+-152) for y1e =================
__global__ void k_margin() {
    int row = blockIdx.x;
    int t = threadIdx.x;                        // 0..303
    float* __restrict__ yr = g_y1e + (size_t)row * YE_STRIDE + MARG;
    float y0 = yr[0], yl = yr[T_LEN - 1];
    if (t < MARG) {
        int u = t - MARG;
        yr[u] = 2.0f * y0 - yr[-u];
    } else {
        int u = T_LEN + (t - MARG);
        yr[u] = 2.0f * yl - yr[2 * T_LEN - 2 - u];
    }
}

// ================= K4: 301-tap symmetric FIR, packed f32x2 =================
// e[i] = g_y1e[row*YE + tb + i], i = 8*tid + 8s + u. acc_k = out pair
// (8*tid+2k, +1); contribution of e: Qt[8s+u-2k], Qt[m] = (C[m-2], C[m-3]).
// Slots s0..s7, STATIC naming: at double-step d'=4s+p, slot (j+2d')%8 =
// Qt[2d'-6+j]; phase-p refill sQ2[4s+4+p] = (Qt[8s+2p+2], Qt[8s+2p+3]).
// Zero rotation MOVs. e tile XOR-swizzled in float4 units.
__global__ __launch_bounds__(256) void k_fir(float* __restrict__ out) {
    __shared__ float4 se4[592];
    __shared__ ulonglong2 sQ2[160];
    int tid = threadIdx.x;
    int row = blockIdx.y;
    int tb  = blockIdx.x * TILE;

    const float4* __restrict__ gy4 =
        reinterpret_cast<const float4*>(g_y1e + (size_t)row * YE_STRIDE + tb);
    for (int f = tid; f < 588; f += 256) {
        float4 v = gy4[f];
        se4[f ^ ((f >> 3) & 7)] = v;
    }
    if (tid < 160) sQ2[tid] = reinterpret_cast<const ulonglong2*>(g_Q)[tid];
    __syncthreads();

    u64 acc0 = 0, acc1 = 0, acc2 = 0, acc3 = 0;
    ulonglong2 t01 = sQ2[0], t23 = sQ2[1], t45 = sQ2[2], t67 = sQ2[3];
    u64 s0 = t01.x, s1 = t01.y, s2 = t23.x, s3 = t23.y;
    u64 s4 = t45.x, s5 = t45.y, s6 = t67.x, s7 = t67.y;

    int f0 = 2 * tid;
    #pragma unroll 1
    for (int s = 0; s < 39; ++s) {
        int fa = f0 + 2 * s;
        int fb = fa + 1;
        float4 eva = se4[fa ^ ((fa >> 3) & 7)];
        float4 evb = se4[fb ^ ((fb >> 3) & 7)];
        u64 e;
        // phase 0: u = 8s, 8s+1
        e = bcast2(eva.x);
        fma2(acc0, s6, e); fma2(acc1, s4, e); fma2(acc2, s2, e); fma2(acc3, s0, e);
        e = bcast2(eva.y);
        fma2(acc0, s7, e); fma2(acc1, s5, e); fma2(acc2, s3, e); fma2(acc3, s1, e);
        { ulonglong2 r = sQ2[4 * s + 4]; s0 = r.x; s1 = r.y; }
        // phase 1: u = 8s+2, 8s+3
        e = bcast2(eva.z);
        fma2(acc0, s0, e); fma2(acc1, s6, e); fma2(acc2, s4, e); fma2(acc3, s2, e);
        e = bcast2(eva.w);
        fma2(acc0, s1, e); fma2(acc1, s7, e); fma2(acc2, s5, e); fma2(acc3, s3, e);
        { ulonglong2 r = sQ2[4 * s + 5]; s2 = r.x; s3 = r.y; }
        // phase 2: u = 8s+4, 8s+5
        e = bcast2(evb.x);
        fma2(acc0, s2, e); fma2(acc1, s0, e); fma2(acc2, s6, e); fma2(acc3, s4, e);
        e = bcast2(evb.y);
        fma2(acc0, s3, e); fma2(acc1, s1, e); fma2(acc2, s7, e); fma2(acc3, s5, e);
        { ulonglong2 r = sQ2[4 * s + 6]; s4 = r.x; s5 = r.y; }
        // phase 3: u = 8s+6, 8s+7
        e = bcast2(evb.z);
        fma2(acc0, s4, e); fma2(acc1, s2, e); fma2(acc2, s0, e); fma2(acc3, s6, e);
        e = bcast2(evb.w);
        fma2(acc0, s5, e); fma2(acc1, s3, e); fma2(acc2, s1, e); fma2(acc3, s7, e);
        { ulonglong2 r = sQ2[4 * s + 7]; s6 = r.x; s7 = r.y; }
    }

    int t0 = tb + tid * 8;
    if (t0 < T_LEN) {                            // T_LEN % 8 == 0 -> all-or-none
        float o0, o1, o2, o3, o4, o5, o6, o7;
        unpack2(acc0, o0, o1); unpack2(acc1, o2, o3);
        unpack2(acc2, o4, o5); unpack2(acc3, o6, o7);
        float4* op = reinterpret_cast<float4*>(out + (size_t)row * T_LEN + t0);
        op[0] = make_float4(o0, o1, o2, o3);
        op[1] = make_float4(o4, o5, o6, o7);
    }
}

// ================= launch =================
extern "C" void kernel_launch(void* const* d_in, const int* in_sizes, int n_in,
                              void* d_out, int out_size) {
    const float* x  = (const float*)d_in[0];
    const float* bn = (const float*)d_in[1];
    const float* an = (const float*)d_in[2];
    const float* zn = (const float*)d_in[3];
    const float* bf = (const float*)d_in[4];
    float* out = (float*)d_out;

    k_coeff<<<1, 320>>>(bf);
    k_fwd<<<ROWS, 128>>>(x, bn, an, zn);
    k_bwd<<<ROWS, 128>>>(bn, an, zn);
    k_margin<<<ROWS, 2 * MARG>>>();
    k_fir<<<dim3(NTILE, ROWS), 256>>>(out);
}